// round 7
// baseline (speedup 1.0000x reference)
#include <cuda_runtime.h>
#include <cstdint>

#define NSPAN  256
#define KKNOW  1024
#define DMODEL 512
#define LMAX   64
#define HID    500
#define NPAIR  (NSPAN * (LMAX + 1))   /* 16640 = 130 * 128 */

// ---------------- scratch (device globals; no allocation) ----------------
__device__ float g_sentinel[NSPAN * DMODEL];
__device__ float g_span_part[NSPAN * DMODEL];   // includes b1, cols [500,512)=0
__device__ float g_know_part[KKNOW * DMODEL];
__device__ float g_sent_part[NSPAN * DMODEL];
__device__ float g_W2t[DMODEL * DMODEL];        // W2^T, tf32, 4-group permuted k
__device__ float g_WsT[DMODEL * DMODEL];        // Ws^T
__device__ float g_W1aT[DMODEL * DMODEL];       // W1a^T
__device__ float g_W1bT[DMODEL * DMODEL];       // W1b^T
__device__ float g_b2p[DMODEL];
__device__ float g_w3p[DMODEL];
__device__ float g_scpart[4 * NPAIR];           // per-N-tile score partials

__device__ __forceinline__ uint32_t f2tf32(float x) {
    uint32_t r;
    asm("cvt.rna.tf32.f32 %0, %1;" : "=r"(r) : "f"(x));
    return r;
}
__device__ __forceinline__ uint32_t smem_u32(const void* p) {
    uint32_t a;
    asm("{ .reg .u64 t; cvta.to.shared.u64 t, %1; cvt.u32.u64 %0, t; }"
        : "=r"(a) : "l"(p));
    return a;
}
__device__ __forceinline__ void mma_tf32(float* c,
                                         uint32_t a0, uint32_t a1, uint32_t a2, uint32_t a3,
                                         uint32_t b0, uint32_t b1) {
    asm volatile(
        "mma.sync.aligned.m16n8k8.row.col.f32.tf32.tf32.f32 "
        "{%0,%1,%2,%3}, {%4,%5,%6,%7}, {%8,%9}, {%0,%1,%2,%3};"
        : "+f"(c[0]), "+f"(c[1]), "+f"(c[2]), "+f"(c[3])
        : "r"(a0), "r"(a1), "r"(a2), "r"(a3), "r"(b0), "r"(b1));
}
#define CP_ASYNC16(dst, src) \
    asm volatile("cp.async.cg.shared.global [%0], [%1], 16;" \
                 :: "r"(dst), "l"(src) : "memory")
#define CP_COMMIT() asm volatile("cp.async.commit_group;" ::: "memory")
#define CP_WAIT(n)  asm volatile("cp.async.wait_group %0;" :: "n"(n) : "memory")

// A-side pair-permutation: PERMC(k) = ((k&3)<<1)+((k>>2)&1)+(k&8)
//   (k, k+4) adjacent -> LDS.64 fragment loads.
// B-side 4-group permutation: PERMB(k) = ((k&3)<<2)|(k>>2)
//   (k, k+4, k+8, k+12) adjacent -> one LDS.128 covers both k-steps.
#define PERMB(c) ((((c) & 3) << 2) | (((c) >> 2) & 3))

// smem word layout (dynamic):
//   As: 2 bufs of 128*24 @ 0, 3072   (PERMC + 4-word XOR swizzle, pitch 24)
//   Bs: 4 bufs of 128*16 @ 6144 + q*2048 (PERMB, pitch 16)
//   sred: 256 floats @ 14336
#define APITCH 24
#define SMEM_WORDS (14336 + 256)
#define SMEM_BYTES (SMEM_WORDS * 4)

// ---------------- prep: transpose+tf32+permute all B matrices, pad b2/w3 ----
__global__ void prep_kernel(const float* __restrict__ W2,
                            const float* __restrict__ Ws,
                            const float* __restrict__ W1,
                            const float* __restrict__ b2,
                            const float* __restrict__ W3) {
    int i = blockIdx.x * blockDim.x + threadIdx.x;   // 0 .. 512*512-1
    int k = i >> 9, n = i & 511;
    int z = blockIdx.y;
    float v;
    float* dst;
    if (z == 0)      { v = (k < HID && n < HID) ? W2[k * HID + n] : 0.f; dst = g_W2t; }
    else if (z == 1) { v = Ws[k * DMODEL + n];                           dst = g_WsT; }
    else if (z == 2) { v = (n < HID) ? W1[k * HID + n] : 0.f;            dst = g_W1aT; }
    else             { v = (n < HID) ? W1[(k + DMODEL) * HID + n] : 0.f; dst = g_W1bT; }
    dst[n * DMODEL + (k & ~15) + PERMB(k & 15)] = __uint_as_float(f2tf32(v));
    if (z == 0 && i < DMODEL) {
        g_b2p[i] = (i < HID) ? b2[i] : 0.f;
        g_w3p[i] = (i < HID) ? W3[i] : 0.f;
    }
}

// ================= unified pipelined tf32 mma GEMM core =================
// CTA tile 128(M) x 128(N), K=512 in 32 chunks of 16.
// 128 threads = 4 warps (2M x 2N), warp tile 64x64, acc[4][8][4] = 128 regs.
// A: reg prefetch of a full 16-float row/thread (+relu/add for PAIR),
//    raw fp32 (HMMA truncates to tf32) -> swizzled smem (2 bufs).
// B: cp.async from pre-permuted global (4 bufs, static indices); each B
//    fragment is ONE LDS.128 reused across all 4 mi tiles.
template<bool PAIR>
__device__ __forceinline__ void gemm_core(
    const float* __restrict__ arp1, const float* __restrict__ arp2,
    const float* __restrict__ Bt,
    const float* __restrict__ bias, float* __restrict__ C, int N, int relu) {
    extern __shared__ uint32_t sm[];
    const int tid = threadIdx.x;
    const int lane = tid & 31, wid = tid >> 5;
    const int gid = lane >> 2, tig = lane & 3;
    const int wm = wid >> 1, wn = wid & 1;        // 2M x 2N warps
    const int m0 = blockIdx.y * 128, n0 = blockIdx.x * 128;

    const float* brp = Bt + (size_t)(n0 + tid) * DMODEL;

    uint32_t su = smem_u32(sm);
    uint32_t bdst[4];
#pragma unroll
    for (int q = 0; q < 4; q++)
        bdst[q] = su + (uint32_t)(6144 + q * 2048 + tid * 16) * 4;

    const int swst = ((tid >> 2) & 3) << 2;       // store-side XOR swizzle

    float acc[4][8][4];
#pragma unroll
    for (int mi = 0; mi < 4; mi++)
#pragma unroll
        for (int ni = 0; ni < 8; ni++)
#pragma unroll
            for (int q = 0; q < 4; q++) acc[mi][ni][q] = 0.f;

    float4 pa1[4], pa2[4];

#define LDA(s) do { int _k = (s) * 16;                                        \
    _Pragma("unroll") for (int i = 0; i < 4; i++) {                           \
        pa1[i] = *(const float4*)(arp1 + _k + i * 4);                         \
        if (PAIR) pa2[i] = *(const float4*)(arp2 + _k + i * 4);               \
    } } while (0)

#define STA(b) do {                                                           \
    uint32_t* _d = sm + (b) * 3072 + tid * APITCH;                            \
    float w[16];                                                              \
    _Pragma("unroll") for (int i = 0; i < 4; i++) {                           \
        if (PAIR) {                                                           \
            w[i*4+0] = fmaxf(pa1[i].x + pa2[i].x, 0.f);                       \
            w[i*4+1] = fmaxf(pa1[i].y + pa2[i].y, 0.f);                       \
            w[i*4+2] = fmaxf(pa1[i].z + pa2[i].z, 0.f);                       \
            w[i*4+3] = fmaxf(pa1[i].w + pa2[i].w, 0.f);                       \
        } else {                                                              \
            w[i*4+0] = pa1[i].x; w[i*4+1] = pa1[i].y;                         \
            w[i*4+2] = pa1[i].z; w[i*4+3] = pa1[i].w;                         \
        }                                                                     \
    }                                                                         \
    uint4 q0 = make_uint4(__float_as_uint(w[0]),  __float_as_uint(w[4]),      \
                          __float_as_uint(w[1]),  __float_as_uint(w[5]));     \
    uint4 q1 = make_uint4(__float_as_uint(w[2]),  __float_as_uint(w[6]),      \
                          __float_as_uint(w[3]),  __float_as_uint(w[7]));     \
    uint4 q2 = make_uint4(__float_as_uint(w[8]),  __float_as_uint(w[12]),     \
                          __float_as_uint(w[9]),  __float_as_uint(w[13]));    \
    uint4 q3 = make_uint4(__float_as_uint(w[10]), __float_as_uint(w[14]),     \
                          __float_as_uint(w[11]), __float_as_uint(w[15]));    \
    *(uint4*)&_d[0 ^ swst]  = q0;                                             \
    *(uint4*)&_d[4 ^ swst]  = q1;                                             \
    *(uint4*)&_d[8 ^ swst]  = q2;                                             \
    *(uint4*)&_d[12 ^ swst] = q3; } while (0)

// always commits (possibly-empty group) so CP_WAIT counts stay static
#define LDB(s, q) do { if ((s) < 32) { int _k = (s) * 16;                     \
        CP_ASYNC16(bdst[q],      brp + _k);                                   \
        CP_ASYNC16(bdst[q] + 16, brp + _k + 4);                               \
        CP_ASYNC16(bdst[q] + 32, brp + _k + 8);                               \
        CP_ASYNC16(bdst[q] + 48, brp + _k + 12); }                            \
    CP_COMMIT(); } while (0)

#define COMPUTE(AB, BB) do {                                                  \
    const uint32_t* A_ = sm + (AB) * 3072;                                    \
    const uint32_t* B_ = sm + 6144 + (BB) * 2048;                             \
    uint4 bfr[8];                                                             \
    _Pragma("unroll") for (int ni = 0; ni < 8; ni++) {                        \
        int nr = wn * 64 + ni * 8 + gid;                                      \
        bfr[ni] = *(const uint4*)&B_[nr * 16 + tig * 4];                      \
    }                                                                         \
    _Pragma("unroll") for (int mi = 0; mi < 4; mi++) {                        \
        int r0 = wm * 64 + mi * 16 + gid;                                     \
        int r1 = r0 + 8;                                                      \
        int sw0 = ((r0 >> 2) & 3) << 2;                                       \
        int sw1 = ((r1 >> 2) & 3) << 2;                                       \
        uint2 a00 = *(const uint2*)&A_[r0 * APITCH + ((tig * 2) ^ sw0)];      \
        uint2 a01 = *(const uint2*)&A_[r1 * APITCH + ((tig * 2) ^ sw1)];      \
        uint2 a10 = *(const uint2*)&A_[r0 * APITCH + ((8 + tig * 2) ^ sw0)];  \
        uint2 a11 = *(const uint2*)&A_[r1 * APITCH + ((8 + tig * 2) ^ sw1)];  \
        _Pragma("unroll") for (int ni = 0; ni < 8; ni++) {                    \
            mma_tf32(acc[mi][ni], a00.x, a01.x, a00.y, a01.y,                 \
                     bfr[ni].x, bfr[ni].y);                                   \
            mma_tf32(acc[mi][ni], a10.x, a11.x, a10.y, a11.y,                 \
                     bfr[ni].z, bfr[ni].w);                                   \
        }                                                                     \
    } } while (0)

#define ITER(s, AB, BB) do {                                                  \
    if ((s) + 1 < 32) STA((AB) ^ 1);                                          \
    if ((s) + 2 < 32) LDA((s) + 2);                                           \
    LDB((s) + 3, ((BB) + 3) & 3);                                             \
    CP_WAIT(2);                                                               \
    COMPUTE(AB, BB);                                                          \
    __syncthreads(); } while (0)

    // prologue: chunk0 -> A0, B groups 0..2 in flight, chunk1 in regs
    LDA(0); STA(0);
    LDB(0, 0); LDB(1, 1); LDB(2, 2);
    LDA(1);
    CP_WAIT(2);
    __syncthreads();

    // main: s = 0..27 (all guards true), static buffer indices
#pragma unroll 1
    for (int s0 = 0; s0 < 28; s0 += 4) {
        ITER(s0 + 0, 0, 0);
        ITER(s0 + 1, 1, 1);
        ITER(s0 + 2, 0, 2);
        ITER(s0 + 3, 1, 3);
    }
    // tail: s = 28..31
    ITER(28, 0, 0);
    ITER(29, 1, 1);
    ITER(30, 0, 2);
    ITER(31, 1, 3);

#undef LDA
#undef STA
#undef LDB
#undef COMPUTE
#undef ITER

    if (PAIR) {
        float* sred = (float*)(sm + 14336);
#pragma unroll
        for (int mi = 0; mi < 4; mi++) {
            float p0 = 0.f, p1 = 0.f;
#pragma unroll
            for (int ni = 0; ni < 8; ni++) {
                int nn = n0 + wn * 64 + ni * 8 + 2 * tig;
                float b2a = g_b2p[nn],     w3a = g_w3p[nn];
                float b2b = g_b2p[nn + 1], w3b = g_w3p[nn + 1];
                p0 += fmaxf(acc[mi][ni][0] + b2a, 0.f) * w3a
                    + fmaxf(acc[mi][ni][1] + b2b, 0.f) * w3b;
                p1 += fmaxf(acc[mi][ni][2] + b2a, 0.f) * w3a
                    + fmaxf(acc[mi][ni][3] + b2b, 0.f) * w3b;
            }
            p0 += __shfl_xor_sync(0xFFFFFFFFu, p0, 1);
            p0 += __shfl_xor_sync(0xFFFFFFFFu, p0, 2);
            p1 += __shfl_xor_sync(0xFFFFFFFFu, p1, 1);
            p1 += __shfl_xor_sync(0xFFFFFFFFu, p1, 2);
            if (tig == 0) {
                int r = wm * 64 + mi * 16 + gid;
                sred[r * 2 + wn] = p0;
                sred[(r + 8) * 2 + wn] = p1;
            }
        }
        __syncthreads();
        g_scpart[blockIdx.x * NPAIR + m0 + tid] = sred[tid * 2] + sred[tid * 2 + 1];
    } else {
#pragma unroll
        for (int mi = 0; mi < 4; mi++) {
            int r = m0 + wm * 64 + mi * 16 + gid;
#pragma unroll
            for (int ni = 0; ni < 8; ni++) {
                int nn = n0 + wn * 64 + ni * 8 + 2 * tig;
                float ba = (bias && nn < N) ? bias[nn] : 0.f;
                float bb = (bias && nn + 1 < N) ? bias[nn + 1] : 0.f;
                float c0 = (nn < N) ? acc[mi][ni][0] + ba : 0.f;
                float c1 = (nn + 1 < N) ? acc[mi][ni][1] + bb : 0.f;
                float c2 = (nn < N) ? acc[mi][ni][2] + ba : 0.f;
                float c3 = (nn + 1 < N) ? acc[mi][ni][3] + bb : 0.f;
                if (relu) {
                    c0 = fmaxf(c0, 0.f); c1 = fmaxf(c1, 0.f);
                    c2 = fmaxf(c2, 0.f); c3 = fmaxf(c3, 0.f);
                }
                *(float2*)&C[(size_t)r * DMODEL + nn] = make_float2(c0, c1);
                *(float2*)&C[(size_t)(r + 8) * DMODEL + nn] = make_float2(c2, c3);
            }
        }
    }
}

// ---------------- kernel wrappers ----------------
__global__ void __launch_bounds__(128, 2) pair_mma_kernel(const int* __restrict__ s2c) {
    int p = blockIdx.y * 128 + threadIdx.x;
    int nsp = p / 65, l = p - nsp * 65;
    const float* a1 = g_span_part + (size_t)nsp * DMODEL;
    const float* a2 = (l < LMAX)
        ? g_know_part + (size_t)s2c[nsp * LMAX + l] * DMODEL
        : g_sent_part + (size_t)nsp * DMODEL;
    gemm_core<true>(a1, a2, g_W2t, nullptr, nullptr, 0, 0);
}

__global__ void __launch_bounds__(128, 2) sentinel_kernel(
    const float* __restrict__ span, const float* __restrict__ bs) {
    const float* a1 = span + (size_t)(blockIdx.y * 128 + threadIdx.x) * DMODEL;
    gemm_core<false>(a1, a1, g_WsT, bs, g_sentinel, DMODEL, 1);
}

// span_part / know_part / sent_part (sent depends on sentinel_kernel)
__global__ void __launch_bounds__(128, 2) small_multi_kernel(
    const float* __restrict__ span, const float* __restrict__ know,
    const float* __restrict__ b1) {
    int z = blockIdx.z;
    if (z != 1 && blockIdx.y >= 2) return;
    const float* A; const float* Bt; const float* bias; float* C;
    if (z == 0)      { A = span;       Bt = g_W1aT; bias = b1;      C = g_span_part; }
    else if (z == 1) { A = know;       Bt = g_W1bT; bias = nullptr; C = g_know_part; }
    else             { A = g_sentinel; Bt = g_W1bT; bias = nullptr; C = g_sent_part; }
    const float* a1 = A + (size_t)(blockIdx.y * 128 + threadIdx.x) * DMODEL;
    gemm_core<false>(a1, a1, Bt, bias, C, HID, 0);
}

// ---------------- softmax + feature aggregation ----------------
__global__ void __launch_bounds__(128) softmax_features_kernel(
    const int* __restrict__ s2c, const int* __restrict__ lengths,
    const float* __restrict__ know, float* __restrict__ out) {
    int n = blockIdx.x;
    int t = threadIdx.x;
    __shared__ float sc[65];
    __shared__ const float* eptr[65];
    __shared__ float redmax, redinv;

    if (t < 65) {
        float s = 0.f;
#pragma unroll
        for (int q = 0; q < 4; q++) s += g_scpart[q * NPAIR + n * 65 + t];
        bool valid;
        const float* ep;
        if (t < LMAX) {
            int len = lengths[n];
            if (len < 1) len = 1;
            valid = t < len;
            int idx = s2c[n * LMAX + t];
            ep = know + (size_t)idx * DMODEL;
        } else {
            valid = true;
            ep = g_sentinel + (size_t)n * DMODEL;
        }
        sc[t] = valid ? s : -1e30f;
        eptr[t] = ep;
    }
    __syncthreads();
    if (t == 0) {
        float m = sc[0];
        for (int l = 1; l < 65; l++) m = fmaxf(m, sc[l]);
        redmax = m;
    }
    __syncthreads();
    float m = redmax;
    if (t < 65) sc[t] = expf(sc[t] - m);
    __syncthreads();
    if (t == 0) {
        float s = 0.f;
        for (int l = 0; l < 65; l++) s += sc[l];
        redinv = 1.f / s;
    }
    __syncthreads();
    if (t < 65) {
        sc[t] *= redinv;
        out[NSPAN * DMODEL + n * 65 + t] = sc[t];   // probs
    }
    __syncthreads();
    float a0 = 0.f, a1 = 0.f, a2 = 0.f, a3 = 0.f;
    for (int l = 0; l < 65; l++) {
        float p = sc[l];
        const float* ep = eptr[l];
        a0 += p * ep[t];
        a1 += p * ep[t + 128];
        a2 += p * ep[t + 256];
        a3 += p * ep[t + 384];
    }
    out[n * DMODEL + t]       = a0;   // features
    out[n * DMODEL + t + 128] = a1;
    out[n * DMODEL + t + 256] = a2;
    out[n * DMODEL + t + 384] = a3;
}

// ---------------- launch ----------------
extern "C" void kernel_launch(void* const* d_in, const int* in_sizes, int n_in,
                              void* d_out, int out_size) {
    const float* span    = (const float*)d_in[0];
    const float* know    = (const float*)d_in[1];
    const int*   s2c     = (const int*)d_in[2];
    const int*   lengths = (const int*)d_in[3];
    const float* Ws      = (const float*)d_in[4];
    const float* bs      = (const float*)d_in[5];
    const float* W1      = (const float*)d_in[6];
    const float* b1      = (const float*)d_in[7];
    const float* W2      = (const float*)d_in[8];
    const float* b2      = (const float*)d_in[9];
    const float* W3      = (const float*)d_in[10];
    // d_in[11] = b3: softmax-invariant constant shift, intentionally unused.
    float* out = (float*)d_out;

    cudaFuncSetAttribute(pair_mma_kernel,
                         cudaFuncAttributeMaxDynamicSharedMemorySize, SMEM_BYTES);
    cudaFuncSetAttribute(sentinel_kernel,
                         cudaFuncAttributeMaxDynamicSharedMemorySize, SMEM_BYTES);
    cudaFuncSetAttribute(small_multi_kernel,
                         cudaFuncAttributeMaxDynamicSharedMemorySize, SMEM_BYTES);

    // transpose+permute+tf32 all B matrices
    prep_kernel<<<dim3(1024, 4), 256>>>(W2, Ws, W1, b2, W3);
    // sentinel first (small, unblocks sent_part)
    sentinel_kernel<<<dim3(4, 2), 128, SMEM_BYTES>>>(span, bs);
    // span_part / know_part / sent_part concurrently
    small_multi_kernel<<<dim3(4, 8, 3), 128, SMEM_BYTES>>>(span, know, b1);
    // fused h1 -> h2 -> score partials
    pair_mma_kernel<<<dim3(4, 130), 128, SMEM_BYTES>>>(s2c);
    // softmax + features
    softmax_features_kernel<<<NSPAN, 128>>>(s2c, lengths, know, out);
}

// round 8
// speedup vs baseline: 1.1447x; 1.1447x over previous
#include <cuda_runtime.h>
#include <cstdint>

#define NSPAN  256
#define KKNOW  1024
#define DMODEL 512
#define LMAX   64
#define HID    500
#define NPAIR  (NSPAN * (LMAX + 1))   /* 16640 = 130 * 128 */

// ---------------- scratch (device globals; no allocation) ----------------
__device__ float g_sentinel[NSPAN * DMODEL];
__device__ float g_span_part[NSPAN * DMODEL];   // includes b1, cols [500,512)=0
__device__ float g_know_part[KKNOW * DMODEL];
__device__ float g_sent_part[NSPAN * DMODEL];
__device__ float g_W2t[DMODEL * DMODEL];        // W2^T, tf32, 4-group permuted k
__device__ float g_WsT[DMODEL * DMODEL];        // Ws^T
__device__ float g_W1aT[DMODEL * DMODEL];       // W1a^T
__device__ float g_W1bT[DMODEL * DMODEL];       // W1b^T
__device__ float g_b2p[DMODEL];
__device__ float g_w3p[DMODEL];
__device__ float g_scpart[2 * NPAIR];           // per-N-half score partials

__device__ __forceinline__ uint32_t f2tf32(float x) {
    uint32_t r;
    asm("cvt.rna.tf32.f32 %0, %1;" : "=r"(r) : "f"(x));
    return r;
}
__device__ __forceinline__ uint32_t smem_u32(const void* p) {
    uint32_t a;
    asm("{ .reg .u64 t; cvta.to.shared.u64 t, %1; cvt.u32.u64 %0, t; }"
        : "=r"(a) : "l"(p));
    return a;
}
__device__ __forceinline__ void mma_tf32(float* c,
                                         uint32_t a0, uint32_t a1, uint32_t a2, uint32_t a3,
                                         uint32_t b0, uint32_t b1) {
    asm volatile(
        "mma.sync.aligned.m16n8k8.row.col.f32.tf32.tf32.f32 "
        "{%0,%1,%2,%3}, {%4,%5,%6,%7}, {%8,%9}, {%0,%1,%2,%3};"
        : "+f"(c[0]), "+f"(c[1]), "+f"(c[2]), "+f"(c[3])
        : "r"(a0), "r"(a1), "r"(a2), "r"(a3), "r"(b0), "r"(b1));
}
#define CP_ASYNC16(dst, src) \
    asm volatile("cp.async.cg.shared.global [%0], [%1], 16;" \
                 :: "r"(dst), "l"(src) : "memory")
#define CP_COMMIT() asm volatile("cp.async.commit_group;" ::: "memory")
#define CP_WAIT(n)  asm volatile("cp.async.wait_group %0;" :: "n"(n) : "memory")

// B-side 4-group permutation ((k, k+4, k+8, k+12) adjacent) — LDS.128 fragments
#define PERMB(c) ((((c) & 3) << 2) | (((c) >> 2) & 3))

// smem word layout (dynamic):
//   As: 2 bufs of 128*24 @ 0, 3072      (pair-perm, pitch 24, conflict-free)
//   Bs: 4 bufs of 128*16 @ 6144 + q*2048 (PERMB, pitch 16)
//   sred: 256 floats @ 14336
#define APITCH 24
#define SMEM_WORDS (14336 + 256)
#define SMEM_BYTES (SMEM_WORDS * 4)

// ---------------- prep: transpose+tf32+permute all B matrices, pad b2/w3 ----
__global__ void prep_kernel(const float* __restrict__ W2,
                            const float* __restrict__ Ws,
                            const float* __restrict__ W1,
                            const float* __restrict__ b2,
                            const float* __restrict__ W3) {
    int i = blockIdx.x * blockDim.x + threadIdx.x;   // 0 .. 512*512-1
    int k = i >> 9, n = i & 511;
    int z = blockIdx.y;
    float v;
    float* dst;
    if (z == 0)      { v = (k < HID && n < HID) ? W2[k * HID + n] : 0.f; dst = g_W2t; }
    else if (z == 1) { v = Ws[k * DMODEL + n];                           dst = g_WsT; }
    else if (z == 2) { v = (n < HID) ? W1[k * HID + n] : 0.f;            dst = g_W1aT; }
    else             { v = (n < HID) ? W1[(k + DMODEL) * HID + n] : 0.f; dst = g_W1bT; }
    dst[n * DMODEL + (k & ~15) + PERMB(k & 15)] = __uint_as_float(f2tf32(v));
    if (z == 0 && i < DMODEL) {
        g_b2p[i] = (i < HID) ? b2[i] : 0.f;
        g_w3p[i] = (i < HID) ? W3[i] : 0.f;
    }
}

// ================= unified pipelined tf32 mma GEMM core (R6 shape) =========
// CTA tile 128(M) x 128(N), K=512 in 32 chunks of 16.
// 256 threads = 8 warps (4M x 2N), warp tile 32x64, acc[2][8][4].
// A: reg prefetch (+relu/add for PAIR), raw fp32 (HMMA truncates) -> smem.
// B: cp.async from pre-permuted global (4 bufs, static indices).
// PAIR mode: accumulates score partials into sred (caller zero-inits & stores).
template<bool PAIR>
__device__ __forceinline__ void gemm_core(
    int m0, int n0,
    const float* __restrict__ arp1, const float* __restrict__ arp2,
    const float* __restrict__ Bt,
    const float* __restrict__ bias, float* __restrict__ C, int N, int relu) {
    extern __shared__ uint32_t sm[];
    const int tid = threadIdx.x;
    const int lane = tid & 31, wid = tid >> 5;
    const int gid = lane >> 2, tig = lane & 3;
    const int wm = wid >> 1, wn = wid & 1;        // 4M x 2N warps
    const int arow = tid >> 1, ah = (tid & 1) * 8;

    const float* brp = Bt + (size_t)(n0 + arow) * DMODEL + ah;
    arp1 += ah;
    arp2 += ah;

    uint32_t su = smem_u32(sm);
    uint32_t bdst[4];
#pragma unroll
    for (int q = 0; q < 4; q++)
        bdst[q] = su + (uint32_t)(6144 + q * 2048 + arow * 16 + ah) * 4;

    float acc[2][8][4];
#pragma unroll
    for (int mi = 0; mi < 2; mi++)
#pragma unroll
        for (int ni = 0; ni < 8; ni++)
#pragma unroll
            for (int q = 0; q < 4; q++) acc[mi][ni][q] = 0.f;

    float4 pa1[2], pa2[2];

#define LDA(s) do { int _k = (s) * 16;                                        \
    pa1[0] = *(const float4*)(arp1 + _k);                                     \
    pa1[1] = *(const float4*)(arp1 + _k + 4);                                 \
    if (PAIR) {                                                               \
        pa2[0] = *(const float4*)(arp2 + _k);                                 \
        pa2[1] = *(const float4*)(arp2 + _k + 4);                             \
    } } while (0)

#define STA(b) do {                                                           \
    uint32_t* _d = sm + (b) * 3072 + arow * APITCH + ah;                      \
    float w0, w1, w2, w3, w4, w5, w6, w7;                                     \
    if (PAIR) {                                                               \
        w0 = fmaxf(pa1[0].x + pa2[0].x, 0.f);                                 \
        w1 = fmaxf(pa1[0].y + pa2[0].y, 0.f);                                 \
        w2 = fmaxf(pa1[0].z + pa2[0].z, 0.f);                                 \
        w3 = fmaxf(pa1[0].w + pa2[0].w, 0.f);                                 \
        w4 = fmaxf(pa1[1].x + pa2[1].x, 0.f);                                 \
        w5 = fmaxf(pa1[1].y + pa2[1].y, 0.f);                                 \
        w6 = fmaxf(pa1[1].z + pa2[1].z, 0.f);                                 \
        w7 = fmaxf(pa1[1].w + pa2[1].w, 0.f);                                 \
    } else {                                                                  \
        w0 = pa1[0].x; w1 = pa1[0].y; w2 = pa1[0].z; w3 = pa1[0].w;           \
        w4 = pa1[1].x; w5 = pa1[1].y; w6 = pa1[1].z; w7 = pa1[1].w;           \
    }                                                                         \
    uint4 q0 = make_uint4(__float_as_uint(w0), __float_as_uint(w4),           \
                          __float_as_uint(w1), __float_as_uint(w5));          \
    uint4 q1 = make_uint4(__float_as_uint(w2), __float_as_uint(w6),           \
                          __float_as_uint(w3), __float_as_uint(w7));          \
    *(uint4*)&_d[0] = q0;                                                     \
    *(uint4*)&_d[4] = q1; } while (0)

// always commits (possibly-empty group) so CP_WAIT counts stay static
#define LDB(s, q) do { if ((s) < 32) { int _k = (s) * 16;                     \
        CP_ASYNC16(bdst[q], brp + _k);                                        \
        CP_ASYNC16(bdst[q] + 16, brp + _k + 4); }                             \
    CP_COMMIT(); } while (0)

#define COMPUTE(AB, BB) do {                                                  \
    const uint32_t* A_ = sm + (AB) * 3072;                                    \
    const uint32_t* B_ = sm + 6144 + (BB) * 2048;                             \
    uint2 aa[2][2][2];                                                        \
    _Pragma("unroll") for (int ks = 0; ks < 2; ks++)                          \
    _Pragma("unroll") for (int mi = 0; mi < 2; mi++) {                        \
        int r = wm * 32 + mi * 16 + gid;                                      \
        int kko = ks * 8 + tig * 2;                                           \
        aa[ks][mi][0] = *(const uint2*)&A_[r * APITCH + kko];                 \
        aa[ks][mi][1] = *(const uint2*)&A_[(r + 8) * APITCH + kko];           \
    }                                                                         \
    _Pragma("unroll") for (int ni = 0; ni < 8; ni++) {                        \
        int nr = wn * 64 + ni * 8 + gid;                                      \
        uint4 b = *(const uint4*)&B_[nr * 16 + tig * 4];                      \
        mma_tf32(acc[0][ni], aa[0][0][0].x, aa[0][0][1].x,                    \
                 aa[0][0][0].y, aa[0][0][1].y, b.x, b.y);                     \
        mma_tf32(acc[1][ni], aa[0][1][0].x, aa[0][1][1].x,                    \
                 aa[0][1][0].y, aa[0][1][1].y, b.x, b.y);                     \
        mma_tf32(acc[0][ni], aa[1][0][0].x, aa[1][0][1].x,                    \
                 aa[1][0][0].y, aa[1][0][1].y, b.z, b.w);                     \
        mma_tf32(acc[1][ni], aa[1][1][0].x, aa[1][1][1].x,                    \
                 aa[1][1][0].y, aa[1][1][1].y, b.z, b.w);                     \
    } } while (0)

#define ITER(s, AB, BB) do {                                                  \
    if ((s) + 1 < 32) STA((AB) ^ 1);                                          \
    if ((s) + 2 < 32) LDA((s) + 2);                                           \
    LDB((s) + 3, ((BB) + 3) & 3);                                             \
    CP_WAIT(2);                                                               \
    COMPUTE(AB, BB);                                                          \
    __syncthreads(); } while (0)

    // prologue: chunk0 -> A0, B groups 0..2 in flight, chunk1 in regs
    LDA(0); STA(0);
    LDB(0, 0); LDB(1, 1); LDB(2, 2);
    LDA(1);
    CP_WAIT(2);
    __syncthreads();

    // main: s = 0..27 (all guards true), static buffer indices
#pragma unroll 1
    for (int s0 = 0; s0 < 28; s0 += 4) {
        ITER(s0 + 0, 0, 0);
        ITER(s0 + 1, 1, 1);
        ITER(s0 + 2, 0, 2);
        ITER(s0 + 3, 1, 3);
    }
    // tail: s = 28..31
    ITER(28, 0, 0);
    ITER(29, 1, 1);
    ITER(30, 0, 2);
    ITER(31, 1, 3);

#undef LDA
#undef STA
#undef LDB
#undef COMPUTE
#undef ITER

    if (PAIR) {
        // accumulate per-row score partials over this 128-col tile into sred
        float* sred = (float*)(sm + 14336);
#pragma unroll
        for (int mi = 0; mi < 2; mi++) {
            float p0 = 0.f, p1 = 0.f;
#pragma unroll
            for (int ni = 0; ni < 8; ni++) {
                int nn = n0 + wn * 64 + ni * 8 + 2 * tig;
                float b2a = g_b2p[nn],     w3a = g_w3p[nn];
                float b2b = g_b2p[nn + 1], w3b = g_w3p[nn + 1];
                p0 += fmaxf(acc[mi][ni][0] + b2a, 0.f) * w3a
                    + fmaxf(acc[mi][ni][1] + b2b, 0.f) * w3b;
                p1 += fmaxf(acc[mi][ni][2] + b2a, 0.f) * w3a
                    + fmaxf(acc[mi][ni][3] + b2b, 0.f) * w3b;
            }
            p0 += __shfl_xor_sync(0xFFFFFFFFu, p0, 1);
            p0 += __shfl_xor_sync(0xFFFFFFFFu, p0, 2);
            p1 += __shfl_xor_sync(0xFFFFFFFFu, p1, 1);
            p1 += __shfl_xor_sync(0xFFFFFFFFu, p1, 2);
            if (tig == 0) {
                int r = wm * 32 + mi * 16 + gid;
                sred[r * 2 + wn] += p0;
                sred[(r + 8) * 2 + wn] += p1;
            }
        }
        __syncthreads();
    } else {
#pragma unroll
        for (int mi = 0; mi < 2; mi++) {
            int r = m0 + wm * 32 + mi * 16 + gid;
#pragma unroll
            for (int ni = 0; ni < 8; ni++) {
                int nn = n0 + wn * 64 + ni * 8 + 2 * tig;
                float ba = (bias && nn < N) ? bias[nn] : 0.f;
                float bb = (bias && nn + 1 < N) ? bias[nn + 1] : 0.f;
                float c0 = (nn < N) ? acc[mi][ni][0] + ba : 0.f;
                float c1 = (nn + 1 < N) ? acc[mi][ni][1] + bb : 0.f;
                float c2 = (nn < N) ? acc[mi][ni][2] + ba : 0.f;
                float c3 = (nn + 1 < N) ? acc[mi][ni][3] + bb : 0.f;
                if (relu) {
                    c0 = fmaxf(c0, 0.f); c1 = fmaxf(c1, 0.f);
                    c2 = fmaxf(c2, 0.f); c3 = fmaxf(c3, 0.f);
                }
                *(float2*)&C[(size_t)r * DMODEL + nn] = make_float2(c0, c1);
                *(float2*)&C[(size_t)(r + 8) * DMODEL + nn] = make_float2(c2, c3);
            }
        }
    }
}

// ---------------- kernel wrappers ----------------
// pair: grid (2, 130) — single wave of 260 CTAs, each covering 2 N-tiles.
__global__ void __launch_bounds__(256, 2) pair_mma_kernel(const int* __restrict__ s2c) {
    extern __shared__ uint32_t sm[];
    int m0 = blockIdx.y * 128;
    int row = threadIdx.x >> 1;
    int p = m0 + row, nsp = p / 65, l = p - nsp * 65;
    const float* a1 = g_span_part + (size_t)nsp * DMODEL;
    const float* a2 = (l < LMAX)
        ? g_know_part + (size_t)s2c[nsp * LMAX + l] * DMODEL
        : g_sent_part + (size_t)nsp * DMODEL;

    float* sred = (float*)(sm + 14336);
    sred[threadIdx.x] = 0.f;             // zero partial accumulators
    int n0 = blockIdx.x * 256;
    gemm_core<true>(m0, n0,       a1, a2, g_W2t, nullptr, nullptr, 0, 0);
    gemm_core<true>(m0, n0 + 128, a1, a2, g_W2t, nullptr, nullptr, 0, 0);
    if (threadIdx.x < 128)
        g_scpart[blockIdx.x * NPAIR + m0 + threadIdx.x] =
            sred[threadIdx.x * 2] + sred[threadIdx.x * 2 + 1];
}

// sentinel / span_part / know_part in one launch (z dispatch)
__global__ void __launch_bounds__(256, 2) small_multi_kernel(
    const float* __restrict__ span, const float* __restrict__ know,
    const float* __restrict__ bs, const float* __restrict__ b1) {
    int z = blockIdx.z;
    if (z < 2 && blockIdx.y >= 2) return;
    const float* A; const float* Bt; const float* bias; float* C; int N; int relu;
    if (z == 0)      { A = span; Bt = g_WsT;  bias = bs;      C = g_sentinel;  N = DMODEL; relu = 1; }
    else if (z == 1) { A = span; Bt = g_W1aT; bias = b1;      C = g_span_part; N = HID;    relu = 0; }
    else             { A = know; Bt = g_W1bT; bias = nullptr; C = g_know_part; N = HID;    relu = 0; }
    int m0 = blockIdx.y * 128;
    const float* a1 = A + (size_t)(m0 + (threadIdx.x >> 1)) * DMODEL;
    gemm_core<false>(m0, blockIdx.x * 128, a1, a1, Bt, bias, C, N, relu);
}

__global__ void __launch_bounds__(256, 2) small_sent_kernel() {
    int m0 = blockIdx.y * 128;
    const float* a1 = g_sentinel + (size_t)(m0 + (threadIdx.x >> 1)) * DMODEL;
    gemm_core<false>(m0, blockIdx.x * 128, a1, a1, g_W1bT, nullptr, g_sent_part, HID, 0);
}

// ---------------- softmax + feature aggregation ----------------
__global__ void __launch_bounds__(128) softmax_features_kernel(
    const int* __restrict__ s2c, const int* __restrict__ lengths,
    const float* __restrict__ know, float* __restrict__ out) {
    int n = blockIdx.x;
    int t = threadIdx.x;
    __shared__ float sc[65];
    __shared__ const float* eptr[65];
    __shared__ float redmax, redinv;

    if (t < 65) {
        float s = 0.f;
#pragma unroll
        for (int q = 0; q < 2; q++) s += g_scpart[q * NPAIR + n * 65 + t];
        bool valid;
        const float* ep;
        if (t < LMAX) {
            int len = lengths[n];
            if (len < 1) len = 1;
            valid = t < len;
            int idx = s2c[n * LMAX + t];
            ep = know + (size_t)idx * DMODEL;
        } else {
            valid = true;
            ep = g_sentinel + (size_t)n * DMODEL;
        }
        sc[t] = valid ? s : -1e30f;
        eptr[t] = ep;
    }
    __syncthreads();
    if (t == 0) {
        float m = sc[0];
        for (int l = 1; l < 65; l++) m = fmaxf(m, sc[l]);
        redmax = m;
    }
    __syncthreads();
    float m = redmax;
    if (t < 65) sc[t] = expf(sc[t] - m);
    __syncthreads();
    if (t == 0) {
        float s = 0.f;
        for (int l = 0; l < 65; l++) s += sc[l];
        redinv = 1.f / s;
    }
    __syncthreads();
    if (t < 65) {
        sc[t] *= redinv;
        out[NSPAN * DMODEL + n * 65 + t] = sc[t];   // probs
    }
    __syncthreads();
    float a0 = 0.f, a1 = 0.f, a2 = 0.f, a3 = 0.f;
    for (int l = 0; l < 65; l++) {
        float p = sc[l];
        const float* ep = eptr[l];
        a0 += p * ep[t];
        a1 += p * ep[t + 128];
        a2 += p * ep[t + 256];
        a3 += p * ep[t + 384];
    }
    out[n * DMODEL + t]       = a0;   // features
    out[n * DMODEL + t + 128] = a1;
    out[n * DMODEL + t + 256] = a2;
    out[n * DMODEL + t + 384] = a3;
}

// ---------------- launch ----------------
extern "C" void kernel_launch(void* const* d_in, const int* in_sizes, int n_in,
                              void* d_out, int out_size) {
    const float* span    = (const float*)d_in[0];
    const float* know    = (const float*)d_in[1];
    const int*   s2c     = (const int*)d_in[2];
    const int*   lengths = (const int*)d_in[3];
    const float* Ws      = (const float*)d_in[4];
    const float* bs      = (const float*)d_in[5];
    const float* W1      = (const float*)d_in[6];
    const float* b1      = (const float*)d_in[7];
    const float* W2      = (const float*)d_in[8];
    const float* b2      = (const float*)d_in[9];
    const float* W3      = (const float*)d_in[10];
    // d_in[11] = b3: softmax-invariant constant shift, intentionally unused.
    float* out = (float*)d_out;

    cudaFuncSetAttribute(pair_mma_kernel,
                         cudaFuncAttributeMaxDynamicSharedMemorySize, SMEM_BYTES);
    cudaFuncSetAttribute(small_multi_kernel,
                         cudaFuncAttributeMaxDynamicSharedMemorySize, SMEM_BYTES);
    cudaFuncSetAttribute(small_sent_kernel,
                         cudaFuncAttributeMaxDynamicSharedMemorySize, SMEM_BYTES);

    // transpose+permute+tf32 all B matrices
    prep_kernel<<<dim3(1024, 4), 256>>>(W2, Ws, W1, b2, W3);
    // sentinel / span_part / know_part concurrently
    small_multi_kernel<<<dim3(4, 8, 3), 256, SMEM_BYTES>>>(span, know, bs, b1);
    // sent_part = sentinel @ W1b
    small_sent_kernel<<<dim3(4, 2), 256, SMEM_BYTES>>>();
    // fused h1 -> h2 -> score partials (single wave: 260 CTAs)
    pair_mma_kernel<<<dim3(2, 130), 256, SMEM_BYTES>>>(s2c);
    // softmax + features
    softmax_features_kernel<<<NSPAN, 128>>>(s2c, lengths, know, out);
}